// round 13
// baseline (speedup 1.0000x reference)
#include <cuda_runtime.h>
#include <cuda_fp16.h>
#include <math.h>

#define LQ    2048
#define BQ    8
#define DQ    1024
#define NDIMQ 16
#define NP    8             // packed f32x2 pairs
#define KDQ   (2*DQ)
#define CQ    32
#define CLQ   (LQ/CQ)       // 64
#define BD    (BQ*DQ)       // 8192
#define FTB   128           // final_kernel threads/block

typedef unsigned long long u64;

__device__ __forceinline__ u64 pack2(float lo, float hi) {
    u64 r; asm("mov.b64 %0,{%1,%2};" : "=l"(r) : "f"(lo), "f"(hi)); return r;
}
__device__ __forceinline__ void unpack2(u64 v, float& lo, float& hi) {
    asm("mov.b64 {%0,%1},%2;" : "=f"(lo), "=f"(hi) : "l"(v));
}
__device__ __forceinline__ u64 fma2(u64 a, u64 b, u64 c) {
    u64 d; asm("fma.rn.f32x2 %0,%1,%2,%3;" : "=l"(d) : "l"(a), "l"(b), "l"(c)); return d;
}
__device__ __forceinline__ u64 add2(u64 a, u64 b) {
    u64 d; asm("add.rn.f32x2 %0,%1,%2;" : "=l"(d) : "l"(a), "l"(b)); return d;
}

// Coefficients (fp32)
__device__ float g_q [KDQ*NDIMQ];
__device__ float g_c [KDQ*NDIMQ];
__device__ float g_qp[KDQ*NDIMQ];
// fp16 scratch: state, overwritten in place by carry. layout [dir][chunk][s][n]
__device__ __half g_state[2][CQ*BD*NDIMQ];

__global__ __launch_bounds__(256) void coeff_kernel(
    const float* __restrict__ damp, const float* __restrict__ decay,
    const float* __restrict__ ema,  const float* __restrict__ proj)
{
    int i = blockIdx.x * blockDim.x + threadIdx.x;
    if (i >= KDQ*NDIMQ) return;
    float p  = 1.f / (1.f + expf(-damp[i]));
    float sd = 1.f / (1.f + expf(-decay[i]));
    float q  = 1.f - p * sd;
    g_q[i]  = q;
    g_c[i]  = p * ema[i] * proj[i] * 0.25f;   // 1/sqrt(16)
    g_qp[i] = powf(q, (float)CLQ);
}

// Chunk-local boundary states, both directions fused per thread.
// States stored as fp16 (2x uint4 per direction). Force 4 blocks/SM.
__global__ __launch_bounds__(256, 4) void state_kernel(
    const float* __restrict__ x, const int* __restrict__ mask)
{
    int idx   = blockIdx.x * blockDim.x + threadIdx.x;   // BD*CQ
    int d     = idx & (DQ-1);
    int b     = (idx >> 10) & (BQ-1);
    int chunk = idx >> 13;
    int s     = b*DQ + d;
    int t0    = chunk * CLQ;

    __shared__ __align__(16) float sm[CLQ];
    if (threadIdx.x < CLQ)
        sm[threadIdx.x] = (float)mask[b*LQ + t0 + threadIdx.x];
    __syncthreads();

    // ---- ascending: forward local state ----
    {
        u64 q[NP], h[NP];
        const float2* qv = (const float2*)&g_q[d*NDIMQ];
#pragma unroll
        for (int p = 0; p < NP; p++) { float2 t = qv[p]; q[p] = pack2(t.x, t.y); h[p] = 0ull; }
        for (int j0 = 0; j0 < CLQ; j0 += 8) {
            float xr[8];
#pragma unroll
            for (int k = 0; k < 8; k++) xr[k] = x[(t0+j0+k)*BD + s];
#pragma unroll
            for (int k = 0; k < 8; k++) {
                float xv = xr[k] * sm[j0+k];
                u64 xp = pack2(xv, xv);
#pragma unroll
                for (int p = 0; p < NP; p++) h[p] = fma2(q[p], h[p], xp);
            }
        }
        __half2 hh[NP];
#pragma unroll
        for (int p = 0; p < NP; p++) {
            float lo, hi; unpack2(h[p], lo, hi);
            hh[p] = __floats2half2_rn(lo, hi);
        }
        uint4* dst = (uint4*)&g_state[0][(chunk*BD + s)*NDIMQ];
        dst[0] = *(uint4*)&hh[0];
        dst[1] = *(uint4*)&hh[4];
    }
    // ---- descending: backward local state (x re-read is L1-hot) ----
    {
        u64 q[NP], g[NP];
        const float2* qv = (const float2*)&g_q[(d+DQ)*NDIMQ];
#pragma unroll
        for (int p = 0; p < NP; p++) { float2 t = qv[p]; q[p] = pack2(t.x, t.y); g[p] = 0ull; }
        int te = t0 + CLQ - 1;
        for (int j0 = 0; j0 < CLQ; j0 += 8) {
            float xr[8];
#pragma unroll
            for (int k = 0; k < 8; k++) xr[k] = x[(te-j0-k)*BD + s];
#pragma unroll
            for (int k = 0; k < 8; k++) {
                float xv = xr[k] * sm[CLQ-1-j0-k];
                u64 xp = pack2(xv, xv);
#pragma unroll
                for (int p = 0; p < NP; p++) g[p] = fma2(q[p], g[p], xp);
            }
        }
        __half2 gg[NP];
#pragma unroll
        for (int p = 0; p < NP; p++) {
            float lo, hi; unpack2(g[p], lo, hi);
            gg[p] = __floats2half2_rn(lo, hi);
        }
        uint4* dst = (uint4*)&g_state[1][(chunk*BD + s)*NDIMQ];
        dst[0] = *(uint4*)&gg[0];
        dst[1] = *(uint4*)&gg[4];
    }
}

// Inter-chunk scan IN PLACE: g_state[dir] becomes the carry (state entering
// each chunk). acc kept in fp32; scratch stays L2-resident (16 MB).
__global__ __launch_bounds__(256) void carry_kernel()
{
    int idx = blockIdx.x * blockDim.x + threadIdx.x;   // 2*BD*NDIMQ
    int n   = idx & (NDIMQ-1);
    int d   = (idx >> 4) & (DQ-1);
    int b   = (idx >> 14) & (BQ-1);
    int dir = idx >> 17;
    int s   = b*DQ + d;
    int row = d + dir*DQ;
    int off = s*NDIMQ + n;

    float qp = g_qp[row*NDIMQ + n];
    __half* buf = g_state[dir];
    float acc = 0.f;
    if (dir == 0) {
#pragma unroll
        for (int c = 0; c < CQ; c++) {
            int o = c*(BD*NDIMQ) + off;
            float tmp = __half2float(buf[o]);
            buf[o] = __float2half_rn(acc);
            acc = fmaf(qp, acc, tmp);
        }
    } else {
#pragma unroll
        for (int c = CQ-1; c >= 0; c--) {
            int o = c*(BD*NDIMQ) + off;
            float tmp = __half2float(buf[o]);
            buf[o] = __float2half_rn(acc);
            acc = fmaf(qp, acc, tmp);
        }
    }
}

// Fused final: fwd sweep stages s1 + x*rw in SMEM, bwd sweep adds s2 + silu,
// single streaming out store. Force 7 blocks/SM (28 warps).
__global__ __launch_bounds__(FTB, 7) void final_kernel(
    const float* __restrict__ x, const int* __restrict__ mask,
    const float* __restrict__ rw, float* __restrict__ out)
{
    extern __shared__ float o_s[];            // CLQ*FTB floats = 32 KB
    __shared__ __align__(16) float sm[CLQ];

    int idx   = blockIdx.x * blockDim.x + threadIdx.x;   // BD*CQ
    int tid   = threadIdx.x;
    int d     = idx & (DQ-1);
    int b     = (idx >> 10) & (BQ-1);
    int chunk = idx >> 13;
    int s     = b*DQ + d;
    int t0    = chunk * CLQ;

    if (tid < CLQ)
        sm[tid] = (float)mask[b*LQ + t0 + tid];
    __syncthreads();

    // ---- forward sweep (results staged in smem) ----
    {
        u64 q[NP], c[NP], h[NP];
        const float2* qv = (const float2*)&g_q[d*NDIMQ];
        const float2* cv = (const float2*)&g_c[d*NDIMQ];
        const __half2* car = (const __half2*)&g_state[0][(chunk*BD + s)*NDIMQ];
#pragma unroll
        for (int p = 0; p < NP; p++) {
            float2 tq = qv[p]; q[p] = pack2(tq.x, tq.y);
            float2 tc = cv[p]; c[p] = pack2(tc.x, tc.y);
            float2 th = __half22float2(car[p]);
            h[p] = pack2(th.x, th.y);
        }
        float w = rw[d];
        for (int j0 = 0; j0 < CLQ; j0 += 8) {
            float xr[8];
#pragma unroll
            for (int k = 0; k < 8; k++) xr[k] = x[(t0+j0+k)*BD + s];
#pragma unroll
            for (int k = 0; k < 8; k++) {
                float xv = xr[k] * sm[j0+k];
                u64 xp = pack2(xv, xv);
#pragma unroll
                for (int p = 0; p < NP; p++) h[p] = fma2(q[p], h[p], xp);
                u64 a0 = fma2(c[0], h[0], 0ull);
                u64 a1 = fma2(c[1], h[1], 0ull);
                u64 a2 = fma2(c[2], h[2], 0ull);
                u64 a3 = fma2(c[3], h[3], 0ull);
                a0 = fma2(c[4], h[4], a0);
                a1 = fma2(c[5], h[5], a1);
                a2 = fma2(c[6], h[6], a2);
                a3 = fma2(c[7], h[7], a3);
                a0 = add2(a0, a1); a2 = add2(a2, a3); a0 = add2(a0, a2);
                float lo, hi; unpack2(a0, lo, hi);
                o_s[(j0+k)*FTB + tid] = (lo + hi) + xr[k]*w;
            }
        }
    }
    // ---- backward sweep + silu + single streaming store ----
    {
        u64 q[NP], c[NP], g[NP];
        int row = d + DQ;
        const float2* qv = (const float2*)&g_q[row*NDIMQ];
        const float2* cv = (const float2*)&g_c[row*NDIMQ];
        const __half2* car = (const __half2*)&g_state[1][(chunk*BD + s)*NDIMQ];
#pragma unroll
        for (int p = 0; p < NP; p++) {
            float2 tq = qv[p]; q[p] = pack2(tq.x, tq.y);
            float2 tc = cv[p]; c[p] = pack2(tc.x, tc.y);
            float2 tg = __half22float2(car[p]);
            g[p] = pack2(tg.x, tg.y);
        }
        int te = t0 + CLQ - 1;
        for (int j0 = 0; j0 < CLQ; j0 += 8) {
            float xr[8];
#pragma unroll
            for (int k = 0; k < 8; k++) xr[k] = x[(te-j0-k)*BD + s];
#pragma unroll
            for (int k = 0; k < 8; k++) {
                float xv = xr[k] * sm[CLQ-1-j0-k];
                u64 xp = pack2(xv, xv);
#pragma unroll
                for (int p = 0; p < NP; p++) g[p] = fma2(q[p], g[p], xp);
                u64 a0 = fma2(c[0], g[0], 0ull);
                u64 a1 = fma2(c[1], g[1], 0ull);
                u64 a2 = fma2(c[2], g[2], 0ull);
                u64 a3 = fma2(c[3], g[3], 0ull);
                a0 = fma2(c[4], g[4], a0);
                a1 = fma2(c[5], g[5], a1);
                a2 = fma2(c[6], g[6], a2);
                a3 = fma2(c[7], g[7], a3);
                a0 = add2(a0, a1); a2 = add2(a2, a3); a0 = add2(a0, a2);
                float lo, hi; unpack2(a0, lo, hi);
                float v = o_s[(CLQ-1-j0-k)*FTB + tid] + lo + hi;
                __stcs(&out[(te-j0-k)*BD + s], v * (1.f / (1.f + __expf(-v))));
            }
        }
    }
}

extern "C" void kernel_launch(void* const* d_in, const int* in_sizes, int n_in,
                              void* d_out, int out_size)
{
    const float* x     = (const float*)d_in[0];
    const float* damp  = (const float*)d_in[1];
    const float* decay = (const float*)d_in[2];
    const float* ema   = (const float*)d_in[3];
    const float* proj  = (const float*)d_in[4];
    const float* rw    = (const float*)d_in[5];
    const int*   mask  = (const int*)  d_in[6];
    float* out = (float*)d_out;

    const int o_smem = CLQ * FTB * (int)sizeof(float);   // 32 KB
    cudaFuncSetAttribute(final_kernel,
                         cudaFuncAttributeMaxDynamicSharedMemorySize, o_smem);

    coeff_kernel<<<(KDQ*NDIMQ + 255)/256, 256>>>(damp, decay, ema, proj);
    state_kernel<<<(BD*CQ)/256, 256>>>(x, mask);
    carry_kernel<<<(2*BD*NDIMQ)/256, 256>>>();
    final_kernel<<<(BD*CQ)/FTB, FTB, o_smem>>>(x, mask, rw, out);
}

// round 14
// speedup vs baseline: 1.1108x; 1.1108x over previous
#include <cuda_runtime.h>
#include <cuda_fp16.h>
#include <math.h>

#define LQ    2048
#define BQ    8
#define DQ    1024
#define NDIMQ 16
#define NP    8             // packed f32x2 pairs
#define KDQ   (2*DQ)
#define CQ    32
#define CLQ   (LQ/CQ)       // 64
#define BD    (BQ*DQ)       // 8192
#define FTB   128           // final_kernel threads/block

typedef unsigned long long u64;

__device__ __forceinline__ u64 pack2(float lo, float hi) {
    u64 r; asm("mov.b64 %0,{%1,%2};" : "=l"(r) : "f"(lo), "f"(hi)); return r;
}
__device__ __forceinline__ void unpack2(u64 v, float& lo, float& hi) {
    asm("mov.b64 {%0,%1},%2;" : "=f"(lo), "=f"(hi) : "l"(v));
}
__device__ __forceinline__ u64 fma2(u64 a, u64 b, u64 c) {
    u64 d; asm("fma.rn.f32x2 %0,%1,%2,%3;" : "=l"(d) : "l"(a), "l"(b), "l"(c)); return d;
}
__device__ __forceinline__ u64 add2(u64 a, u64 b) {
    u64 d; asm("add.rn.f32x2 %0,%1,%2;" : "=l"(d) : "l"(a), "l"(b)); return d;
}

// Coefficients (fp32)
__device__ float g_q [KDQ*NDIMQ];
__device__ float g_c [KDQ*NDIMQ];
__device__ float g_qp[KDQ*NDIMQ];
// fp16 scratch: state, overwritten in place by carry. layout [dir][chunk][s][n]
__device__ __half g_state[2][CQ*BD*NDIMQ];

__global__ __launch_bounds__(256) void coeff_kernel(
    const float* __restrict__ damp, const float* __restrict__ decay,
    const float* __restrict__ ema,  const float* __restrict__ proj)
{
    int i = blockIdx.x * blockDim.x + threadIdx.x;
    if (i >= KDQ*NDIMQ) return;
    float p  = 1.f / (1.f + expf(-damp[i]));
    float sd = 1.f / (1.f + expf(-decay[i]));
    float q  = 1.f - p * sd;
    g_q[i]  = q;
    g_c[i]  = p * ema[i] * proj[i] * 0.25f;   // 1/sqrt(16)
    g_qp[i] = powf(q, (float)CLQ);
}

// Chunk-local boundary states, both directions fused per thread.
// States stored as fp16 (2x uint4 per direction).
__global__ __launch_bounds__(256, 3) void state_kernel(
    const float* __restrict__ x, const int* __restrict__ mask)
{
    int idx   = blockIdx.x * blockDim.x + threadIdx.x;   // BD*CQ
    int d     = idx & (DQ-1);
    int b     = (idx >> 10) & (BQ-1);
    int chunk = idx >> 13;
    int s     = b*DQ + d;
    int t0    = chunk * CLQ;

    __shared__ __align__(16) float sm[CLQ];
    if (threadIdx.x < CLQ)
        sm[threadIdx.x] = (float)mask[b*LQ + t0 + threadIdx.x];
    __syncthreads();

    // ---- ascending: forward local state ----
    {
        u64 q[NP], h[NP];
        const float2* qv = (const float2*)&g_q[d*NDIMQ];
#pragma unroll
        for (int p = 0; p < NP; p++) { float2 t = qv[p]; q[p] = pack2(t.x, t.y); h[p] = 0ull; }
        for (int j0 = 0; j0 < CLQ; j0 += 8) {
            float xr[8], mm[8];
            float4 m0 = *(const float4*)&sm[j0];
            float4 m1 = *(const float4*)&sm[j0+4];
            mm[0]=m0.x; mm[1]=m0.y; mm[2]=m0.z; mm[3]=m0.w;
            mm[4]=m1.x; mm[5]=m1.y; mm[6]=m1.z; mm[7]=m1.w;
#pragma unroll
            for (int k = 0; k < 8; k++) xr[k] = x[(t0+j0+k)*BD + s];
#pragma unroll
            for (int k = 0; k < 8; k++) {
                float xv = xr[k] * mm[k];
                u64 xp = pack2(xv, xv);
#pragma unroll
                for (int p = 0; p < NP; p++) h[p] = fma2(q[p], h[p], xp);
            }
        }
        __half2 hh[NP];
#pragma unroll
        for (int p = 0; p < NP; p++) {
            float lo, hi; unpack2(h[p], lo, hi);
            hh[p] = __floats2half2_rn(lo, hi);
        }
        uint4* dst = (uint4*)&g_state[0][(chunk*BD + s)*NDIMQ];
        dst[0] = *(uint4*)&hh[0];
        dst[1] = *(uint4*)&hh[4];
    }
    // ---- descending: backward local state (x re-read is L1-hot) ----
    {
        u64 q[NP], g[NP];
        const float2* qv = (const float2*)&g_q[(d+DQ)*NDIMQ];
#pragma unroll
        for (int p = 0; p < NP; p++) { float2 t = qv[p]; q[p] = pack2(t.x, t.y); g[p] = 0ull; }
        int te = t0 + CLQ - 1;
        for (int j0 = 0; j0 < CLQ; j0 += 8) {
            float xr[8], mm[8];
            int base = CLQ - 8 - j0;
            float4 m0 = *(const float4*)&sm[base];
            float4 m1 = *(const float4*)&sm[base+4];
            mm[0]=m0.x; mm[1]=m0.y; mm[2]=m0.z; mm[3]=m0.w;
            mm[4]=m1.x; mm[5]=m1.y; mm[6]=m1.z; mm[7]=m1.w;
#pragma unroll
            for (int k = 0; k < 8; k++) xr[k] = x[(te-j0-k)*BD + s];
#pragma unroll
            for (int k = 0; k < 8; k++) {
                float xv = xr[k] * mm[7-k];
                u64 xp = pack2(xv, xv);
#pragma unroll
                for (int p = 0; p < NP; p++) g[p] = fma2(q[p], g[p], xp);
            }
        }
        __half2 gg[NP];
#pragma unroll
        for (int p = 0; p < NP; p++) {
            float lo, hi; unpack2(g[p], lo, hi);
            gg[p] = __floats2half2_rn(lo, hi);
        }
        uint4* dst = (uint4*)&g_state[1][(chunk*BD + s)*NDIMQ];
        dst[0] = *(uint4*)&gg[0];
        dst[1] = *(uint4*)&gg[4];
    }
}

// Inter-chunk scan IN PLACE, half2-vectorized: each thread owns an n-pair.
__global__ __launch_bounds__(256) void carry_kernel()
{
    int idx = blockIdx.x * blockDim.x + threadIdx.x;   // 2*BD*NDIMQ/2
    int np_ = idx & (NDIMQ/2 - 1);                     // half2 index 0..7
    int d   = (idx >> 3) & (DQ-1);
    int b   = (idx >> 13) & (BQ-1);
    int dir = idx >> 16;
    int s   = b*DQ + d;
    int row = d + dir*DQ;

    float2 qp2 = *(const float2*)&g_qp[row*NDIMQ + np_*2];
    __half2* buf = (__half2*)g_state[dir];
    int off = s*(NDIMQ/2) + np_;
    const int cstride = BD*(NDIMQ/2);
    float2 acc = make_float2(0.f, 0.f);
    if (dir == 0) {
#pragma unroll
        for (int c = 0; c < CQ; c++) {
            int o = c*cstride + off;
            float2 tmp = __half22float2(buf[o]);
            buf[o] = __floats2half2_rn(acc.x, acc.y);
            acc.x = fmaf(qp2.x, acc.x, tmp.x);
            acc.y = fmaf(qp2.y, acc.y, tmp.y);
        }
    } else {
#pragma unroll
        for (int c = CQ-1; c >= 0; c--) {
            int o = c*cstride + off;
            float2 tmp = __half22float2(buf[o]);
            buf[o] = __floats2half2_rn(acc.x, acc.y);
            acc.x = fmaf(qp2.x, acc.x, tmp.x);
            acc.y = fmaf(qp2.y, acc.y, tmp.y);
        }
    }
}

// Fused final: fwd sweep stages s1 + x*rw in SMEM, bwd sweep adds s2 + silu,
// single streaming out store. 2-chain reduction (9 packed ops).
__global__ __launch_bounds__(FTB, 6) void final_kernel(
    const float* __restrict__ x, const int* __restrict__ mask,
    const float* __restrict__ rw, float* __restrict__ out)
{
    extern __shared__ float o_s[];            // CLQ*FTB floats = 32 KB
    __shared__ __align__(16) float sm[CLQ];

    int idx   = blockIdx.x * blockDim.x + threadIdx.x;   // BD*CQ
    int tid   = threadIdx.x;
    int d     = idx & (DQ-1);
    int b     = (idx >> 10) & (BQ-1);
    int chunk = idx >> 13;
    int s     = b*DQ + d;
    int t0    = chunk * CLQ;

    if (tid < CLQ)
        sm[tid] = (float)mask[b*LQ + t0 + tid];
    __syncthreads();

    // ---- forward sweep (results staged in smem) ----
    {
        u64 q[NP], c[NP], h[NP];
        const float2* qv = (const float2*)&g_q[d*NDIMQ];
        const float2* cv = (const float2*)&g_c[d*NDIMQ];
        const __half2* car = (const __half2*)&g_state[0][(chunk*BD + s)*NDIMQ];
#pragma unroll
        for (int p = 0; p < NP; p++) {
            float2 tq = qv[p]; q[p] = pack2(tq.x, tq.y);
            float2 tc = cv[p]; c[p] = pack2(tc.x, tc.y);
            float2 th = __half22float2(car[p]);
            h[p] = pack2(th.x, th.y);
        }
        float w = rw[d];
        for (int j0 = 0; j0 < CLQ; j0 += 8) {
            float xr[8], mm[8];
            float4 m0 = *(const float4*)&sm[j0];
            float4 m1 = *(const float4*)&sm[j0+4];
            mm[0]=m0.x; mm[1]=m0.y; mm[2]=m0.z; mm[3]=m0.w;
            mm[4]=m1.x; mm[5]=m1.y; mm[6]=m1.z; mm[7]=m1.w;
#pragma unroll
            for (int k = 0; k < 8; k++) xr[k] = x[(t0+j0+k)*BD + s];
#pragma unroll
            for (int k = 0; k < 8; k++) {
                float xv = xr[k] * mm[k];
                u64 xp = pack2(xv, xv);
#pragma unroll
                for (int p = 0; p < NP; p++) h[p] = fma2(q[p], h[p], xp);
                u64 a0 = fma2(c[0], h[0], 0ull);
                u64 a1 = fma2(c[1], h[1], 0ull);
                a0 = fma2(c[2], h[2], a0);
                a1 = fma2(c[3], h[3], a1);
                a0 = fma2(c[4], h[4], a0);
                a1 = fma2(c[5], h[5], a1);
                a0 = fma2(c[6], h[6], a0);
                a1 = fma2(c[7], h[7], a1);
                a0 = add2(a0, a1);
                float lo, hi; unpack2(a0, lo, hi);
                o_s[(j0+k)*FTB + tid] = (lo + hi) + xr[k]*w;
            }
        }
    }
    // ---- backward sweep + silu + single streaming store ----
    {
        u64 q[NP], c[NP], g[NP];
        int row = d + DQ;
        const float2* qv = (const float2*)&g_q[row*NDIMQ];
        const float2* cv = (const float2*)&g_c[row*NDIMQ];
        const __half2* car = (const __half2*)&g_state[1][(chunk*BD + s)*NDIMQ];
#pragma unroll
        for (int p = 0; p < NP; p++) {
            float2 tq = qv[p]; q[p] = pack2(tq.x, tq.y);
            float2 tc = cv[p]; c[p] = pack2(tc.x, tc.y);
            float2 tg = __half22float2(car[p]);
            g[p] = pack2(tg.x, tg.y);
        }
        int te = t0 + CLQ - 1;
        for (int j0 = 0; j0 < CLQ; j0 += 8) {
            float xr[8], mm[8];
            int base = CLQ - 8 - j0;
            float4 m0 = *(const float4*)&sm[base];
            float4 m1 = *(const float4*)&sm[base+4];
            mm[0]=m0.x; mm[1]=m0.y; mm[2]=m0.z; mm[3]=m0.w;
            mm[4]=m1.x; mm[5]=m1.y; mm[6]=m1.z; mm[7]=m1.w;
#pragma unroll
            for (int k = 0; k < 8; k++) xr[k] = x[(te-j0-k)*BD + s];
#pragma unroll
            for (int k = 0; k < 8; k++) {
                float xv = xr[k] * mm[7-k];
                u64 xp = pack2(xv, xv);
#pragma unroll
                for (int p = 0; p < NP; p++) g[p] = fma2(q[p], g[p], xp);
                u64 a0 = fma2(c[0], g[0], 0ull);
                u64 a1 = fma2(c[1], g[1], 0ull);
                a0 = fma2(c[2], g[2], a0);
                a1 = fma2(c[3], g[3], a1);
                a0 = fma2(c[4], g[4], a0);
                a1 = fma2(c[5], g[5], a1);
                a0 = fma2(c[6], g[6], a0);
                a1 = fma2(c[7], g[7], a1);
                a0 = add2(a0, a1);
                float lo, hi; unpack2(a0, lo, hi);
                float v = o_s[(CLQ-1-j0-k)*FTB + tid] + lo + hi;
                __stcs(&out[(te-j0-k)*BD + s], v * (1.f / (1.f + __expf(-v))));
            }
        }
    }
}

extern "C" void kernel_launch(void* const* d_in, const int* in_sizes, int n_in,
                              void* d_out, int out_size)
{
    const float* x     = (const float*)d_in[0];
    const float* damp  = (const float*)d_in[1];
    const float* decay = (const float*)d_in[2];
    const float* ema   = (const float*)d_in[3];
    const float* proj  = (const float*)d_in[4];
    const float* rw    = (const float*)d_in[5];
    const int*   mask  = (const int*)  d_in[6];
    float* out = (float*)d_out;

    const int o_smem = CLQ * FTB * (int)sizeof(float);   // 32 KB
    cudaFuncSetAttribute(final_kernel,
                         cudaFuncAttributeMaxDynamicSharedMemorySize, o_smem);

    coeff_kernel<<<(KDQ*NDIMQ + 255)/256, 256>>>(damp, decay, ema, proj);
    state_kernel<<<(BD*CQ)/256, 256>>>(x, mask);
    carry_kernel<<<(BD*NDIMQ)/256, 256>>>();
    final_kernel<<<(BD*CQ)/FTB, FTB, o_smem>>>(x, mask, rw, out);
}